// round 2
// baseline (speedup 1.0000x reference)
#include <cuda_runtime.h>
#include <cuda_bf16.h>

#define NB   8
#define NV   2048
#define NF   512
#define VOX  96
#define PLANE (VOX * VOX)          // 9216
#define VTOT  (VOX * VOX * VOX)    // 884736

// Per-facet precomputed record, AoS stride 16 floats (64B):
// [0..2]  = adj row0 * sign(det)
// [3]     = |det|  (or -1.0f if det == 0 -> never inside)
// [4..6]  = adj row1 * sign(det)
// [7]     = v3.x
// [8..10] = adj row2 * sign(det)
// [11]    = v3.y
// [12]    = v3.z
// [13..15]= pad
__device__ float g_fd[NB * NF * 16];

// ---------------------------------------------------------------------------
// Prep: compute adjugate/det per facet, sort facets by |det| descending
// (big tets first -> earlier hits in the voxel kernel). One block per batch.
// ---------------------------------------------------------------------------
__global__ void __launch_bounds__(NF) prep_kernel(
    const float* __restrict__ vertices,   // [NB, NV, 3] f32
    const int*   __restrict__ facets)     // [NB, NF, 4] i32 (JAX x64-off downcast)
{
    __shared__ float sdat[NF * 16];
    __shared__ float skey[NF];
    __shared__ int   sidx[NF];

    const int b = blockIdx.x;
    const int f = threadIdx.x;

    const float* Vb = vertices + (size_t)b * NV * 3;
    const int* Fp = facets + ((size_t)b * NF + f) * 4;
    const int i0 = Fp[0] & (NV - 1);
    const int i1 = Fp[1] & (NV - 1);
    const int i2 = Fp[2] & (NV - 1);
    const int i3 = Fp[3] & (NV - 1);

    const float v0x = Vb[i0*3+0], v0y = Vb[i0*3+1], v0z = Vb[i0*3+2];
    const float v1x = Vb[i1*3+0], v1y = Vb[i1*3+1], v1z = Vb[i1*3+2];
    const float v2x = Vb[i2*3+0], v2y = Vb[i2*3+1], v2z = Vb[i2*3+2];
    const float v3x = Vb[i3*3+0], v3y = Vb[i3*3+1], v3z = Vb[i3*3+2];

    // T columns (reference naming): a..i
    const float a  = v0x - v3x, bb = v1x - v3x, c  = v2x - v3x;
    const float d  = v0y - v3y, e  = v1y - v3y, ff = v2y - v3y;
    const float g  = v0z - v3z, h  = v1z - v3z, ii = v2z - v3z;

    const float A00 = e*ii - ff*h, A01 = c*h  - bb*ii, A02 = bb*ff - c*e;
    const float A10 = ff*g - d*ii, A11 = a*ii - c*g,   A12 = c*d  - a*ff;
    const float A20 = d*h  - e*g,  A21 = bb*g - a*h,   A22 = a*e  - bb*d;

    const float det = a*A00 + bb*A10 + c*A20;

    const float sd   = (det < 0.0f) ? -1.0f : 1.0f;
    float detp = det * sd;
    if (det == 0.0f) detp = -1.0f;   // degenerate -> inside test always false

    float* p = sdat + f * 16;
    p[0]  = A00 * sd;  p[1]  = A01 * sd;  p[2]  = A02 * sd;  p[3]  = detp;
    p[4]  = A10 * sd;  p[5]  = A11 * sd;  p[6]  = A12 * sd;  p[7]  = v3x;
    p[8]  = A20 * sd;  p[9]  = A21 * sd;  p[10] = A22 * sd;  p[11] = v3y;
    p[12] = v3z;       p[13] = 0.0f;      p[14] = 0.0f;      p[15] = 0.0f;

    skey[f] = -detp;   // ascending sort of -|det| == descending |det|
    sidx[f] = f;
    __syncthreads();

    // Bitonic sort, 512 elements / 512 threads
    for (int k = 2; k <= NF; k <<= 1) {
        for (int j = k >> 1; j > 0; j >>= 1) {
            const int partner = f ^ j;
            if (partner > f) {
                const bool up = ((f & k) == 0);
                const float ka = skey[f], kb = skey[partner];
                if ((ka > kb) == up) {
                    skey[f] = kb; skey[partner] = ka;
                    const int tmp = sidx[f]; sidx[f] = sidx[partner]; sidx[partner] = tmp;
                }
            }
            __syncthreads();
        }
    }

    // Write permuted records to global
    const int src = sidx[f];
    float4* go = reinterpret_cast<float4*>(g_fd + (size_t)b * NF * 16);
    const float4* si = reinterpret_cast<const float4*>(sdat);
    #pragma unroll
    for (int w = 0; w < 4; w++)
        go[f * 4 + w] = si[src * 4 + w];
}

// ---------------------------------------------------------------------------
// Voxelize: one block per (batch, x-plane). Block caches all 512 facet
// records in smem; each thread handles 36 voxels with per-voxel early exit.
// ---------------------------------------------------------------------------
__global__ void __launch_bounds__(256) vox_kernel(float* __restrict__ out)
{
    __shared__ float4 sm[NF * 4];   // 32 KB

    const int b     = blockIdx.y;
    const int plane = blockIdx.x;

    const float4* gq = reinterpret_cast<const float4*>(g_fd + (size_t)b * NF * 16);
    for (int w = threadIdx.x; w < NF * 4; w += 256)
        sm[w] = gq[w];
    __syncthreads();

    const float px = (float)(2 * plane + 1 - VOX) / (float)VOX;
    float* ob = out + (size_t)b * VTOT + (size_t)plane * PLANE;
    const float* smf = reinterpret_cast<const float*>(sm);

    for (int t = threadIdx.x; t < PLANE; t += 256) {
        const int j = t / VOX;
        const int k = t - j * VOX;
        const float py = (float)(2 * j + 1 - VOX) / (float)VOX;
        const float pz = (float)(2 * k + 1 - VOX) / (float)VOX;

        float res = 0.0f;
        for (int f = 0; f < NF; f++) {
            const float4 q0 = sm[f * 4 + 0];   // a00 a01 a02 |det|
            const float4 q1 = sm[f * 4 + 1];   // a10 a11 a12 v3x
            const float4 q2 = sm[f * 4 + 2];   // a20 a21 a22 v3y
            const float v3z = smf[f * 16 + 12];

            const float dx = px - q1.w;
            const float dy = py - q2.w;
            const float dz = pz - v3z;

            const float n0 = fmaf(q0.x, dx, fmaf(q0.y, dy, q0.z * dz));
            const float n1 = fmaf(q1.x, dx, fmaf(q1.y, dy, q1.z * dz));
            const float n2 = fmaf(q2.x, dx, fmaf(q2.y, dy, q2.z * dz));
            const float s  = n0 + n1 + n2;

            const float lo = fminf(fminf(n0, n1), fminf(n2, s));
            const float hi = fmaxf(fmaxf(n0, n1), fmaxf(n2, s));

            // inside  <=>  all lambda in [0,1]  <=>  0 <= n_r <= |det| and 0 <= s <= |det|
            if (lo >= 0.0f && hi <= q0.w) { res = 1.0f; break; }
        }
        ob[t] = res;
    }
}

extern "C" void kernel_launch(void* const* d_in, const int* in_sizes, int n_in,
                              void* d_out, int out_size)
{
    const float* vertices = (const float*)d_in[0];   // [8, 2048, 3] f32
    const int*   facets   = (const int*)d_in[1];     // [8, 512, 4]  i32
    float* out = (float*)d_out;                      // [8, 96, 96, 96] f32

    prep_kernel<<<NB, NF>>>(vertices, facets);
    dim3 grid(VOX, NB);
    vox_kernel<<<grid, 256>>>(out);
}

// round 3
// speedup vs baseline: 7.6684x; 7.6684x over previous
#include <cuda_runtime.h>
#include <cuda_bf16.h>

#define NB   8
#define NV   2048
#define NF   512
#define VOX  96
#define PLANE (VOX * VOX)          // 9216
#define VTOT  (VOX * VOX * VOX)    // 884736
#define DELTA 0.03125f

// Exact-test record (R2 layout), sorted order, 4 float4 per facet:
//  e0 = A00 A01 A02 |det|      e1 = A10 A11 A12 v3x
//  e2 = A20 A21 A22 v3y        e3 = v3z pad pad pad
__device__ float4 g_ex[NB * NF * 4];

// Interval record, sorted order, 5 float4 per facet:
//  q0 = A00 A01 K0 nG0     (base_r = A_r0*px + A_r1*py + K_r ; nG = -1/G_r)
//  q1 = A10 A11 K1 nG1
//  q2 = A20 A21 K2 nG2
//  q3 = sA0 sA1 Ks nGs     (s-constraint: sum of rows)
//  q4 = DoG0 DoG1 DoG2 DoGs  (D / G_r)
__device__ float4 g_int[NB * NF * 5];

// ---------------------------------------------------------------------------
// Prep: adjugate/det per facet, sort by |det| descending, emit both records.
// One block of 512 threads per batch.
// ---------------------------------------------------------------------------
__global__ void __launch_bounds__(NF) prep_kernel(
    const float* __restrict__ vertices,   // [NB, NV, 3] f32
    const int*   __restrict__ facets)     // [NB, NF, 4] i32
{
    __shared__ float sdat[NF * 16];
    __shared__ float skey[NF];
    __shared__ int   sidx[NF];

    const int b = blockIdx.x;
    const int f = threadIdx.x;

    const float* Vb = vertices + (size_t)b * NV * 3;
    const int* Fp = facets + ((size_t)b * NF + f) * 4;
    const int i0 = Fp[0] & (NV - 1);
    const int i1 = Fp[1] & (NV - 1);
    const int i2 = Fp[2] & (NV - 1);
    const int i3 = Fp[3] & (NV - 1);

    const float v0x = Vb[i0*3+0], v0y = Vb[i0*3+1], v0z = Vb[i0*3+2];
    const float v1x = Vb[i1*3+0], v1y = Vb[i1*3+1], v1z = Vb[i1*3+2];
    const float v2x = Vb[i2*3+0], v2y = Vb[i2*3+1], v2z = Vb[i2*3+2];
    const float v3x = Vb[i3*3+0], v3y = Vb[i3*3+1], v3z = Vb[i3*3+2];

    const float a  = v0x - v3x, bb = v1x - v3x, c  = v2x - v3x;
    const float d  = v0y - v3y, e  = v1y - v3y, ff = v2y - v3y;
    const float g  = v0z - v3z, h  = v1z - v3z, ii = v2z - v3z;

    const float A00 = e*ii - ff*h, A01 = c*h  - bb*ii, A02 = bb*ff - c*e;
    const float A10 = ff*g - d*ii, A11 = a*ii - c*g,   A12 = c*d  - a*ff;
    const float A20 = d*h  - e*g,  A21 = bb*g - a*h,   A22 = a*e  - bb*d;

    const float det = a*A00 + bb*A10 + c*A20;

    const float sd   = (det < 0.0f) ? -1.0f : 1.0f;
    float detp = det * sd;
    if (det == 0.0f) detp = -1.0f;   // degenerate -> never inside

    float* p = sdat + f * 16;
    p[0]  = A00 * sd;  p[1]  = A01 * sd;  p[2]  = A02 * sd;  p[3]  = detp;
    p[4]  = A10 * sd;  p[5]  = A11 * sd;  p[6]  = A12 * sd;  p[7]  = v3x;
    p[8]  = A20 * sd;  p[9]  = A21 * sd;  p[10] = A22 * sd;  p[11] = v3y;
    p[12] = v3z;       p[13] = 0.0f;      p[14] = 0.0f;      p[15] = 0.0f;

    skey[f] = -detp;   // ascending sort of -|det| == descending |det|
    sidx[f] = f;
    __syncthreads();

    for (int k = 2; k <= NF; k <<= 1) {
        for (int j = k >> 1; j > 0; j >>= 1) {
            const int partner = f ^ j;
            if (partner > f) {
                const bool up = ((f & k) == 0);
                const float ka = skey[f], kb = skey[partner];
                if ((ka > kb) == up) {
                    skey[f] = kb; skey[partner] = ka;
                    const int tmp = sidx[f]; sidx[f] = sidx[partner]; sidx[partner] = tmp;
                }
            }
            __syncthreads();
        }
    }

    const int src = sidx[f];
    const float* q = sdat + src * 16;

    // exact record (sorted)
    {
        float4* go = g_ex + ((size_t)b * NF + f) * 4;
        const float4* si = reinterpret_cast<const float4*>(q);
        go[0] = si[0]; go[1] = si[1]; go[2] = si[2]; go[3] = si[3];
    }

    // interval record
    {
        const float B00=q[0], B01=q[1], B02=q[2], D=q[3];
        const float B10=q[4], B11=q[5], B12=q[6], w3x=q[7];
        const float B20=q[8], B21=q[9], B22=q[10], w3y=q[11];
        const float w3z=q[12];

        const float STEP = 2.0f / (float)VOX;
        const float PZ0  = (1.0f - (float)VOX) / (float)VOX;   // pz at k=0

        const float G0 = B02 * STEP, G1 = B12 * STEP, G2 = B22 * STEP;
        const float K0 = B02*(PZ0 - w3z) - B00*w3x - B01*w3y;
        const float K1 = B12*(PZ0 - w3z) - B10*w3x - B11*w3y;
        const float K2 = B22*(PZ0 - w3z) - B20*w3x - B21*w3y;

        float sA0 = B00 + B10 + B20;
        float sA1 = B01 + B11 + B21;
        float Ks  = K0 + K1 + K2;
        const float Gs = G0 + G1 + G2;

        float nG0 = -1.0f / G0, nG1 = -1.0f / G1, nG2 = -1.0f / G2;
        float nGs = -1.0f / Gs;
        float D0 = D / G0, D1 = D / G1, D2 = D / G2, Ds = D / Gs;

        if (D < 0.0f) {            // degenerate: force-empty via s-constraint
            sA0 = 0.0f; sA1 = 0.0f; Ks = 1.0f; nGs = -2.0f; Ds = 1.0f;
        }

        float4* go = g_int + ((size_t)b * NF + f) * 5;
        go[0] = make_float4(B00, B01, K0, nG0);
        go[1] = make_float4(B10, B11, K1, nG1);
        go[2] = make_float4(B20, B21, K2, nG2);
        go[3] = make_float4(sA0, sA1, Ks, nGs);
        go[4] = make_float4(D0, D1, D2, Ds);
    }
}

// set bits [a, b] (inclusive) of one 32-bit word covering [base, base+32)
__device__ __forceinline__ unsigned range_word(int a, int b, int base)
{
    int lo = a - base;
    int hi = b - base + 1;            // exclusive
    lo = max(lo, 0); hi = min(hi, 32);
    if (lo >= hi) return 0u;
    unsigned mlo = 0xFFFFFFFFu << lo;          // lo in [0,31]
    unsigned mhi = 0xFFFFFFFFu >> (32 - hi);   // hi in [1,32]
    return mlo & mhi;
}

// ---------------------------------------------------------------------------
// Voxelize: one thread = one full z-column (96 voxels) as a 96-bit mask.
// Block = 192 threads = 2 x-planes of 96 y-columns. All facet interval
// records cached in smem; rare boundary voxels re-tested exactly from L2.
// ---------------------------------------------------------------------------
__global__ void __launch_bounds__(192) vox_kernel(float* __restrict__ out)
{
    __shared__ float4 sq[NF * 5];   // 40 KB

    const int b = blockIdx.y;
    const int tid = threadIdx.x;

    {
        const float4* gq = g_int + (size_t)b * NF * 5;
        for (int w = tid; w < NF * 5; w += 192) sq[w] = gq[w];
    }
    __syncthreads();

    const int ix = blockIdx.x * 2 + (tid / 96);
    const int iy = tid % 96;
    const float px = (float)(2 * ix + 1 - VOX) / (float)VOX;
    const float py = (float)(2 * iy + 1 - VOX) / (float)VOX;

    const float4* ex = g_ex + (size_t)b * NF * 4;

    unsigned m0 = 0u, m1 = 0u, m2 = 0u;

    for (int f = 0; f < NF; f++) {
        const float4 q0 = sq[f*5+0];
        const float4 q1 = sq[f*5+1];
        const float4 q2 = sq[f*5+2];
        const float4 q3 = sq[f*5+3];
        const float4 q4 = sq[f*5+4];

        const float b0 = fmaf(q0.x, px, fmaf(q0.y, py, q0.z));
        const float b1 = fmaf(q1.x, px, fmaf(q1.y, py, q1.z));
        const float b2 = fmaf(q2.x, px, fmaf(q2.y, py, q2.z));
        const float b3 = fmaf(q3.x, px, fmaf(q3.y, py, q3.z));

        const float t00 = b0 * q0.w, t01 = t00 + q4.x;
        const float t10 = b1 * q1.w, t11 = t10 + q4.y;
        const float t20 = b2 * q2.w, t21 = t20 + q4.z;
        const float t30 = b3 * q3.w, t31 = t30 + q4.w;

        const float tlo = fmaxf(fmaxf(fminf(t00,t01), fminf(t10,t11)),
                                fmaxf(fminf(t20,t21), fminf(t30,t31)));
        const float thi = fminf(fminf(fmaxf(t00,t01), fmaxf(t10,t11)),
                                fminf(fmaxf(t20,t21), fmaxf(t30,t31)));

        const int kLo = max(0,  __float2int_ru(tlo - DELTA));
        const int kHi = min(95, __float2int_rd(thi + DELTA));

        if (kLo <= kHi) {
            const int cLo = max(kLo, __float2int_ru(tlo + DELTA));
            const int cHi = min(kHi, __float2int_rd(thi - DELTA));

            if (cLo <= cHi) {
                m0 |= range_word(cLo, cHi, 0);
                m1 |= range_word(cLo, cHi, 32);
                m2 |= range_word(cLo, cHi, 64);
            }

            if (kLo < cLo || cHi < kHi) {
                // rare: exact re-test of boundary voxels (reference-identical form)
                const float4 e0 = __ldg(&ex[f*4+0]);
                const float4 e1 = __ldg(&ex[f*4+1]);
                const float4 e2 = __ldg(&ex[f*4+2]);
                const float4 e3 = __ldg(&ex[f*4+3]);
                const float dx = px - e1.w;
                const float dy = py - e2.w;
                for (int k = kLo; k <= kHi; k++) {
                    if (k >= cLo && k <= cHi) { k = cHi; continue; }
                    const float pz = (float)(2 * k + 1 - VOX) / (float)VOX;
                    const float dz = pz - e3.x;
                    const float n0 = fmaf(e0.x, dx, fmaf(e0.y, dy, e0.z * dz));
                    const float n1 = fmaf(e1.x, dx, fmaf(e1.y, dy, e1.z * dz));
                    const float n2 = fmaf(e2.x, dx, fmaf(e2.y, dy, e2.z * dz));
                    const float s  = n0 + n1 + n2;
                    const float lo = fminf(fminf(n0, n1), fminf(n2, s));
                    const float hi = fmaxf(fmaxf(n0, n1), fmaxf(n2, s));
                    if (lo >= 0.0f && hi <= e0.w) {
                        if (k < 32)      m0 |= 1u << k;
                        else if (k < 64) m1 |= 1u << (k - 32);
                        else             m2 |= 1u << (k - 64);
                    }
                }
            }
        }

        if ((f & 7) == 7) {
            const bool done = ((m0 & m1 & m2) == 0xFFFFFFFFu);
            if (__all_sync(0xFFFFFFFFu, done)) break;
        }
    }

    // write 96 floats for this column
    float* ob = out + (((size_t)(b * VOX + ix) * VOX + iy) * VOX);
    float4* o4 = reinterpret_cast<float4*>(ob);
    const unsigned mw[3] = { m0, m1, m2 };
    #pragma unroll
    for (int w = 0; w < 3; w++) {
        const unsigned m = mw[w];
        #pragma unroll
        for (int j = 0; j < 8; j++) {
            float4 v;
            v.x = (m >> (j*4 + 0)) & 1u ? 1.0f : 0.0f;
            v.y = (m >> (j*4 + 1)) & 1u ? 1.0f : 0.0f;
            v.z = (m >> (j*4 + 2)) & 1u ? 1.0f : 0.0f;
            v.w = (m >> (j*4 + 3)) & 1u ? 1.0f : 0.0f;
            o4[w*8 + j] = v;
        }
    }
}

extern "C" void kernel_launch(void* const* d_in, const int* in_sizes, int n_in,
                              void* d_out, int out_size)
{
    const float* vertices = (const float*)d_in[0];   // [8, 2048, 3] f32
    const int*   facets   = (const int*)d_in[1];     // [8, 512, 4]  i32
    float* out = (float*)d_out;                      // [8, 96, 96, 96] f32

    prep_kernel<<<NB, NF>>>(vertices, facets);
    dim3 grid(VOX / 2, NB);                          // 48 x 8 blocks, 192 thr
    vox_kernel<<<grid, 192>>>(out);
}

// round 5
// speedup vs baseline: 27.0523x; 3.5278x over previous
#include <cuda_runtime.h>
#include <cuda_bf16.h>

#define NB   8
#define NV   2048
#define NF   512
#define VOX  96
#define PLANE (VOX * VOX)          // 9216
#define VTOT  (VOX * VOX * VOX)    // 884736
#define DELTA 0.03125f

#define STEPF (2.0f / 96.0f)
#define PZ0F  (-95.0f / 96.0f)

// Exact-test record (bit-identical to R2/R3 form), 4 float4 per facet:
//  e0 = B00 B01 B02 |det|     e1 = B10 B11 B12 v3x
//  e2 = B20 B21 B22 v3y       e3 = v3z pad pad pad
__device__ float4 g_ex[NB * NF * 4];

// Interval record, 4 float4 per facet (rows 0..2 and s-row), lo/hi preordered:
//  q_r = (Ex, Ey, Ec, w) :  lo_r = Ex*px + Ey*py + Ec ;  hi_r = lo_r + w  (w>=0)
__device__ float4 g_int[NB * NF * 4];

// Facet voxel bbox: (ixLo, ixHi, iyLo, iyHi); empty if ixLo > ixHi
__device__ int4 g_bb[NB * NF];

// Column coverage masks: [b][ix*96+iy][3] words of 32 z-bits
__device__ unsigned g_mask[NB * PLANE * 3];

// ---------------------------------------------------------------------------
__global__ void zero_kernel()
{
    const int t = blockIdx.x * 1024 + threadIdx.x;   // 216*1024 = 221184 exact
    g_mask[t] = 0u;
}

// ---------------------------------------------------------------------------
// Prep: one thread per facet. Adjugate/det, exact record, interval record,
// voxel bbox. No sorting (output is an order-independent OR).
// ---------------------------------------------------------------------------
__global__ void prep_kernel(
    const float* __restrict__ vertices,   // [NB, NV, 3] f32
    const int*   __restrict__ facets)     // [NB, NF, 4] i32
{
    const int id = blockIdx.x * 256 + threadIdx.x;   // < NB*NF = 4096
    const int b = id >> 9;

    const float* Vb = vertices + (size_t)b * NV * 3;
    const int* Fp = facets + (size_t)id * 4;
    const int i0 = Fp[0] & (NV - 1);
    const int i1 = Fp[1] & (NV - 1);
    const int i2 = Fp[2] & (NV - 1);
    const int i3 = Fp[3] & (NV - 1);

    const float v0x = Vb[i0*3+0], v0y = Vb[i0*3+1], v0z = Vb[i0*3+2];
    const float v1x = Vb[i1*3+0], v1y = Vb[i1*3+1], v1z = Vb[i1*3+2];
    const float v2x = Vb[i2*3+0], v2y = Vb[i2*3+1], v2z = Vb[i2*3+2];
    const float v3x = Vb[i3*3+0], v3y = Vb[i3*3+1], v3z = Vb[i3*3+2];

    const float a  = v0x - v3x, bb = v1x - v3x, c  = v2x - v3x;
    const float d  = v0y - v3y, e  = v1y - v3y, ff = v2y - v3y;
    const float g  = v0z - v3z, h  = v1z - v3z, ii = v2z - v3z;

    const float A00 = e*ii - ff*h, A01 = c*h  - bb*ii, A02 = bb*ff - c*e;
    const float A10 = ff*g - d*ii, A11 = a*ii - c*g,   A12 = c*d  - a*ff;
    const float A20 = d*h  - e*g,  A21 = bb*g - a*h,   A22 = a*e  - bb*d;

    const float det = a*A00 + bb*A10 + c*A20;
    const float sd  = (det < 0.0f) ? -1.0f : 1.0f;
    float D = det * sd;
    if (det == 0.0f) D = -1.0f;

    const float B[3][3] = { {A00*sd, A01*sd, A02*sd},
                            {A10*sd, A11*sd, A12*sd},
                            {A20*sd, A21*sd, A22*sd} };

    // exact record (same arithmetic form as R2/R3)
    g_ex[id*4+0] = make_float4(B[0][0], B[0][1], B[0][2], D);
    g_ex[id*4+1] = make_float4(B[1][0], B[1][1], B[1][2], v3x);
    g_ex[id*4+2] = make_float4(B[2][0], B[2][1], B[2][2], v3y);
    g_ex[id*4+3] = make_float4(v3z, 0.0f, 0.0f, 0.0f);

    // interval rows: rows 0..2 and the s-row (sum)
    float R0[4], R1[4], Kc[4];   // (B_r0, B_r1) ; K_r
    float Bz[4];
    #pragma unroll
    for (int r = 0; r < 3; r++) {
        R0[r] = B[r][0]; R1[r] = B[r][1];
        float bz = B[r][2];
        if (fabsf(bz) < 1e-30f) bz = 1e-30f;
        Bz[r] = bz;
        Kc[r] = bz * (PZ0F - v3z) - B[r][0]*v3x - B[r][1]*v3y;
    }
    R0[3] = R0[0] + R0[1] + R0[2];
    R1[3] = R1[0] + R1[1] + R1[2];
    {
        float bz = Bz[0] + Bz[1] + Bz[2];
        if (fabsf(bz) < 1e-30f) bz = 1e-30f;
        Bz[3] = bz;
        Kc[3] = Kc[0] + Kc[1] + Kc[2];
    }

    #pragma unroll
    for (int r = 0; r < 4; r++) {
        const float G   = Bz[r] * STEPF;
        const float nG  = -1.0f / G;
        const float DoG = D / G;
        const float Ex  = R0[r] * nG;
        const float Ey  = R1[r] * nG;
        const float Ec  = Kc[r] * nG + fminf(DoG, 0.0f);
        const float w   = fabsf(DoG);
        g_int[id*4+r] = make_float4(Ex, Ey, Ec, w);
    }

    // voxel bbox with safety pad
    const float pad = 1e-5f;
    const float xmn = fminf(fminf(v0x, v1x), fminf(v2x, v3x)) - pad;
    const float xmx = fmaxf(fmaxf(v0x, v1x), fmaxf(v2x, v3x)) + pad;
    const float ymn = fminf(fminf(v0y, v1y), fminf(v2y, v3y)) - pad;
    const float ymx = fmaxf(fmaxf(v0y, v1y), fmaxf(v2y, v3y)) + pad;

    int4 bbv;
    bbv.x = max(0,  (int)ceilf (48.0f * xmn + 47.5f));
    bbv.y = min(95, (int)floorf(48.0f * xmx + 47.5f));
    bbv.z = max(0,  (int)ceilf (48.0f * ymn + 47.5f));
    bbv.w = min(95, (int)floorf(48.0f * ymx + 47.5f));
    if (D < 0.0f) { bbv.x = 1; bbv.y = 0; }   // degenerate: empty
    g_bb[id] = bbv;
}

// ---------------------------------------------------------------------------
// Scatter: one block per facet. Warps take x-rows of the bbox; lanes take y.
// Facet record entirely in registers. Clearly-inside z-range -> bit ranges;
// delta-band voxels re-tested with the exact (R2) formula, then atomicOr.
// ---------------------------------------------------------------------------
__global__ void __launch_bounds__(256) scatter_kernel()
{
    const int id = blockIdx.x;                 // facet global id
    const int4 bbv = g_bb[id];
    if (bbv.x > bbv.y) return;

    const int b = id >> 9;
    const float4 q0 = __ldg(&g_int[id*4+0]);
    const float4 q1 = __ldg(&g_int[id*4+1]);
    const float4 q2 = __ldg(&g_int[id*4+2]);
    const float4 q3 = __ldg(&g_int[id*4+3]);
    const float4 e0 = __ldg(&g_ex[id*4+0]);
    const float4 e1 = __ldg(&g_ex[id*4+1]);
    const float4 e2 = __ldg(&g_ex[id*4+2]);
    const float4 e3 = __ldg(&g_ex[id*4+3]);

    unsigned* gm = g_mask + (size_t)b * PLANE * 3;

    const int warp = threadIdx.x >> 5;
    const int lane = threadIdx.x & 31;
    const int nx = bbv.y - bbv.x + 1;

    for (int r = warp; r < nx; r += 8) {
        const int ix = bbv.x + r;
        const float px = (float)(2 * ix + 1 - VOX) / 96.0f;
        // hoist px-partials
        const float h0 = fmaf(q0.x, px, q0.z);
        const float h1 = fmaf(q1.x, px, q1.z);
        const float h2 = fmaf(q2.x, px, q2.z);
        const float h3 = fmaf(q3.x, px, q3.z);
        const float dx = px - e1.w;

        for (int iy0 = bbv.z; iy0 <= bbv.w; iy0 += 32) {
            const int iy = iy0 + lane;
            if (iy > bbv.w) continue;
            const float py = (float)(2 * iy + 1 - VOX) / 96.0f;

            const float lo0 = fmaf(q0.y, py, h0);
            const float lo1 = fmaf(q1.y, py, h1);
            const float lo2 = fmaf(q2.y, py, h2);
            const float lo3 = fmaf(q3.y, py, h3);
            const float hi0 = lo0 + q0.w;
            const float hi1 = lo1 + q1.w;
            const float hi2 = lo2 + q2.w;
            const float hi3 = lo3 + q3.w;

            const float tlo = fmaxf(fmaxf(lo0, lo1), fmaxf(lo2, lo3));
            const float thi = fminf(fminf(hi0, hi1), fminf(hi2, hi3));

            if (!(thi + DELTA >= tlo - DELTA) || thi < -DELTA || tlo > 95.0f + DELTA)
                continue;

            const int kLo = max(0,  __float2int_ru(tlo - DELTA));
            const int kHi = min(95, __float2int_rd(thi + DELTA));
            if (kLo > kHi) continue;

            const int cLo = max(kLo, __float2int_ru(tlo + DELTA));
            const int cHi = min(kHi, __float2int_rd(thi - DELTA));

            unsigned mw0 = 0u, mw1 = 0u, mw2 = 0u;

            if (cLo <= cHi) {
                #pragma unroll
                for (int w = 0; w < 3; w++) {
                    const int base = 32 * w;
                    int lo_w = min(max(cLo - base, 0), 32);
                    int hi_w = min(max(cHi + 1 - base, 0), 32);
                    unsigned m = 0u;
                    if (lo_w < hi_w)
                        m = (0xFFFFFFFFu >> (32 - (hi_w - lo_w))) << lo_w;
                    if (w == 0) mw0 = m; else if (w == 1) mw1 = m; else mw2 = m;
                }
            }

            if (kLo < cLo || cHi < kHi) {
                // delta-band voxels: exact re-test (reference-identical form)
                const float dy = py - e2.w;
                for (int k = kLo; k <= kHi; k++) {
                    if (k >= cLo && k <= cHi) { k = cHi; continue; }
                    const float pz = (float)(2 * k + 1 - VOX) / 96.0f;
                    const float dz = pz - e3.x;
                    const float n0 = fmaf(e0.x, dx, fmaf(e0.y, dy, e0.z * dz));
                    const float n1 = fmaf(e1.x, dx, fmaf(e1.y, dy, e1.z * dz));
                    const float n2 = fmaf(e2.x, dx, fmaf(e2.y, dy, e2.z * dz));
                    const float s  = n0 + n1 + n2;
                    const float lo = fminf(fminf(n0, n1), fminf(n2, s));
                    const float hi = fmaxf(fmaxf(n0, n1), fmaxf(n2, s));
                    if (lo >= 0.0f && hi <= e0.w) {
                        if (k < 32)      mw0 |= 1u << k;
                        else if (k < 64) mw1 |= 1u << (k - 32);
                        else             mw2 |= 1u << (k - 64);
                    }
                }
            }

            const unsigned col = (unsigned)(ix * VOX + iy) * 3u;
            if (mw0) atomicOr(&gm[col + 0], mw0);
            if (mw1) atomicOr(&gm[col + 1], mw1);
            if (mw2) atomicOr(&gm[col + 2], mw2);
        }
    }
}

// ---------------------------------------------------------------------------
// Expand: one thread per column -> 96 floats (24 float4 stores).
// ---------------------------------------------------------------------------
__global__ void __launch_bounds__(256) expand_kernel(float* __restrict__ out)
{
    const int t = blockIdx.x * 256 + threadIdx.x;    // 288*256 = 73728 exact
    const unsigned* mw = g_mask + (size_t)t * 3;
    const unsigned m0 = mw[0], m1 = mw[1], m2 = mw[2];

    float4* o4 = reinterpret_cast<float4*>(out + (size_t)t * VOX);
    const unsigned mm[3] = { m0, m1, m2 };
    #pragma unroll
    for (int w = 0; w < 3; w++) {
        const unsigned m = mm[w];
        #pragma unroll
        for (int j = 0; j < 8; j++) {
            float4 v;
            v.x = (m >> (j*4 + 0)) & 1u ? 1.0f : 0.0f;
            v.y = (m >> (j*4 + 1)) & 1u ? 1.0f : 0.0f;
            v.z = (m >> (j*4 + 2)) & 1u ? 1.0f : 0.0f;
            v.w = (m >> (j*4 + 3)) & 1u ? 1.0f : 0.0f;
            o4[w*8 + j] = v;
        }
    }
}

extern "C" void kernel_launch(void* const* d_in, const int* in_sizes, int n_in,
                              void* d_out, int out_size)
{
    const float* vertices = (const float*)d_in[0];   // [8, 2048, 3] f32
    const int*   facets   = (const int*)d_in[1];     // [8, 512, 4]  i32
    float* out = (float*)d_out;                      // [8, 96, 96, 96] f32

    zero_kernel<<<216, 1024>>>();                    // 221184 mask words
    prep_kernel<<<16, 256>>>(vertices, facets);      // 4096 facets
    scatter_kernel<<<NB * NF, 256>>>();              // one block per facet
    expand_kernel<<<288, 256>>>(out);                // 73728 columns
}